// round 7
// baseline (speedup 1.0000x reference)
#include <cuda_runtime.h>
#include <cuda_bf16.h>
#include <math.h>
#include <stdint.h>

// ---------------- problem constants ----------------
#define NN      20000
#define EE      160000
#define ETOT    (2*EE + NN)
#define FF      128
#define HH      4
#define CC1     128
#define D1      (HH*CC1)       // 512
#define CC2     256
#define GG      64
#define NCLS    10

// ---------------- device scratch ----------------
__device__ __nv_bfloat16 g_h1[NN * D1];
__device__ float         g_out1[NN * D1];
__device__ __nv_bfloat16 g_h2[NN * CC2];
__device__ float         g_out2[NN * CC2];
__device__ float g_asrc1[NN * HH];
__device__ float g_adst1[NN * HH];
__device__ float g_asrc2[NN];
__device__ float g_adst2[NN];
__device__ int   g_deg[NN];
__device__ int   g_rowptr[NN + 1];
__device__ int   g_wp[NN];
__device__ int   g_col[ETOT];
__device__ int   g_starts[GG + 1];

// ---------------- CSR build ----------------
__global__ void k_init(const int* __restrict__ batch, int n) {
    int i = blockIdx.x * blockDim.x + threadIdx.x;
    if (i < n) {
        g_deg[i] = 1;  // self loop
        if (i == 0) {
            g_starts[batch[0]] = 0;
            g_starts[GG] = n;
        } else if (batch[i] != batch[i - 1]) {
            g_starts[batch[i]] = i;
        }
    }
}

__global__ void k_count_deg(const int* __restrict__ ei, int E) {
    int j = blockIdx.x * blockDim.x + threadIdx.x;
    if (j < E) {
        atomicAdd(&g_deg[ei[j]], 1);
        atomicAdd(&g_deg[ei[E + j]], 1);
    }
}

// single-block full exclusive scan: deg -> rowptr, wp  (n <= 1024*CHUNK)
__global__ __launch_bounds__(1024) void k_scan_fused(int n) {
    const int t = threadIdx.x, lane = t & 31, wid = t >> 5;
    const int chunk = (n + 1023) / 1024;
    int b = t * chunk, e = min(b + chunk, n);
    if (b > n) b = n;
    if (e < b) e = b;

    int s = 0;
    for (int i = b; i < e; i++) s += g_deg[i];

    // block-wide exclusive scan of per-thread sums
    int v = s;
#pragma unroll
    for (int o = 1; o < 32; o <<= 1) {
        int x = __shfl_up_sync(0xffffffffu, v, o);
        if (lane >= o) v += x;
    }
    __shared__ int wtot[32];
    if (lane == 31) wtot[wid] = v;
    __syncthreads();
    if (t < 32) {
        int w = wtot[t];
        int u = w;
#pragma unroll
        for (int o = 1; o < 32; o <<= 1) {
            int x = __shfl_up_sync(0xffffffffu, u, o);
            if (t >= o) u += x;
        }
        wtot[t] = u - w;            // exclusive warp offset
        if (t == 31) g_rowptr[n] = u;  // total
    }
    __syncthreads();
    int run = v - s + wtot[wid];     // exclusive prefix for this thread
    for (int i = b; i < e; i++) {
        int d = g_deg[i];
        g_rowptr[i] = run;
        g_wp[i] = run;
        run += d;
    }
}

__global__ void k_scatter(const int* __restrict__ ei, int E, int n) {
    int j = blockIdx.x * blockDim.x + threadIdx.x;
    if (j < E) {
        int s = ei[j], d = ei[E + j];
        g_col[atomicAdd(&g_wp[d], 1)] = s;
        g_col[atomicAdd(&g_wp[s], 1)] = d;
    } else if (j < E + n) {
        int i = j - E;
        g_col[atomicAdd(&g_wp[i], 1)] = i;
    }
}

// ---------------- tf32 tensor-core GEMM (cp.async 2-stage, bf16 output) ----------------
__device__ __forceinline__ void mma_tf32(float c[4], const unsigned a[4], const unsigned b[2]) {
    asm volatile(
        "mma.sync.aligned.m16n8k8.row.col.f32.tf32.tf32.f32 "
        "{%0,%1,%2,%3}, {%4,%5,%6,%7}, {%8,%9}, {%0,%1,%2,%3};"
        : "+f"(c[0]), "+f"(c[1]), "+f"(c[2]), "+f"(c[3])
        : "r"(a[0]), "r"(a[1]), "r"(a[2]), "r"(a[3]), "r"(b[0]), "r"(b[1]));
}

__device__ __forceinline__ void cp16(uint32_t dst, const float* src, int szbytes) {
    asm volatile("cp.async.ca.shared.global [%0], [%1], 16, %2;\n"
                 :: "r"(dst), "l"(src), "r"(szbytes));
}

#define TBM 128
#define TBN 128
#define TBK 32
#define AS_STRIDE (TBK + 4)
#define BS_STRIDE (TBN + 4)
#define AS_SIZE (TBM * AS_STRIDE)
#define BS_SIZE (TBK * BS_STRIDE)
#define GEMM_SMEM_BYTES (2 * (AS_SIZE + BS_SIZE) * 4)  // 70656

__global__ __launch_bounds__(256) void k_gemm_tf32_bf16out(const float* __restrict__ A,
                                                           const float* __restrict__ B,
                                                           __nv_bfloat16* __restrict__ C,
                                                           int M, int N, int K) {
    extern __shared__ float sm_[];
    float* As = sm_;
    float* Bs = sm_ + 2 * AS_SIZE;
    uint32_t as_base = (uint32_t)__cvta_generic_to_shared(As);
    uint32_t bs_base = (uint32_t)__cvta_generic_to_shared(Bs);

    int tid = threadIdx.x;
    int bm = blockIdx.y * TBM, bn = blockIdx.x * TBN;
    int w = tid >> 5, lane = tid & 31;
    int wy = w & 3, wx = w >> 2;
    int gid = lane >> 2, tig = lane & 3;

    float c[2][8][4];
#pragma unroll
    for (int mt = 0; mt < 2; mt++)
#pragma unroll
        for (int nt = 0; nt < 8; nt++)
#pragma unroll
            for (int r = 0; r < 4; r++) c[mt][nt][r] = 0.f;

    const int KT = K / TBK;

    auto load_tile = [&](int k0, int st) {
#pragma unroll
        for (int i = 0; i < 4; i++) {
            int q = tid + i * 256;
            int row = q >> 3;
            int kk = (q & 7) << 2;
            int gr = bm + row;
            uint32_t d = as_base + (uint32_t)(st * AS_SIZE + row * AS_STRIDE + kk) * 4u;
            cp16(d, &A[(size_t)gr * K + k0 + kk], (gr < M) ? 16 : 0);
        }
#pragma unroll
        for (int i = 0; i < 4; i++) {
            int q = tid + i * 256;
            int kr = q >> 5;
            int nc = (q & 31) << 2;
            uint32_t d = bs_base + (uint32_t)(st * BS_SIZE + kr * BS_STRIDE + nc) * 4u;
            cp16(d, &B[(size_t)(k0 + kr) * N + bn + nc], 16);
        }
        asm volatile("cp.async.commit_group;\n");
    };

    load_tile(0, 0);

    for (int it = 0; it < KT; it++) {
        if (it + 1 < KT) {
            load_tile((it + 1) * TBK, (it + 1) & 1);
            asm volatile("cp.async.wait_group 1;\n");
        } else {
            asm volatile("cp.async.wait_group 0;\n");
        }
        __syncthreads();

        const float* as = As + (it & 1) * AS_SIZE;
        const float* bsm = Bs + (it & 1) * BS_SIZE;
#pragma unroll
        for (int ks = 0; ks < 4; ks++) {
            int kb = ks * 8;
            unsigned af[2][4], bf[8][2];
#pragma unroll
            for (int mt = 0; mt < 2; mt++) {
                int r0 = wy * 32 + mt * 16;
                af[mt][0] = __float_as_uint(as[(r0 + gid) * AS_STRIDE + kb + tig]);
                af[mt][1] = __float_as_uint(as[(r0 + gid + 8) * AS_STRIDE + kb + tig]);
                af[mt][2] = __float_as_uint(as[(r0 + gid) * AS_STRIDE + kb + tig + 4]);
                af[mt][3] = __float_as_uint(as[(r0 + gid + 8) * AS_STRIDE + kb + tig + 4]);
            }
#pragma unroll
            for (int nt = 0; nt < 8; nt++) {
                int c0 = wx * 64 + nt * 8;
                bf[nt][0] = __float_as_uint(bsm[(kb + tig) * BS_STRIDE + c0 + gid]);
                bf[nt][1] = __float_as_uint(bsm[(kb + tig + 4) * BS_STRIDE + c0 + gid]);
            }
#pragma unroll
            for (int mt = 0; mt < 2; mt++)
#pragma unroll
                for (int nt = 0; nt < 8; nt++) mma_tf32(c[mt][nt], af[mt], bf[nt]);
        }
        __syncthreads();
    }

#pragma unroll
    for (int mt = 0; mt < 2; mt++) {
        int r0 = bm + wy * 32 + mt * 16 + gid;
#pragma unroll
        for (int nt = 0; nt < 8; nt++) {
            int cc = bn + wx * 64 + nt * 8 + 2 * tig;
            if (r0 < M) {
                __nv_bfloat162 v = __float22bfloat162_rn(make_float2(c[mt][nt][0], c[mt][nt][1]));
                *(__nv_bfloat162*)&C[(size_t)r0 * N + cc] = v;
            }
            if (r0 + 8 < M) {
                __nv_bfloat162 v = __float22bfloat162_rn(make_float2(c[mt][nt][2], c[mt][nt][3]));
                *(__nv_bfloat162*)&C[(size_t)(r0 + 8) * N + cc] = v;
            }
        }
    }
}

// ---------------- attention dots (bf16 h) ----------------
__global__ void k_attdot1(const __nv_bfloat16* __restrict__ h, const float* __restrict__ as_,
                          const float* __restrict__ ad_, int n) {
    int nid = blockIdx.x;
    int t = threadIdx.x, w = t >> 5, lane = t & 31;
    uint2 raw = *(const uint2*)(h + (size_t)nid * D1 + t * 4);
    float2 f0 = __bfloat1622float2(*reinterpret_cast<__nv_bfloat162*>(&raw.x));
    float2 f1 = __bfloat1622float2(*reinterpret_cast<__nv_bfloat162*>(&raw.y));
    float4 a = *(const float4*)&as_[t * 4];
    float4 b = *(const float4*)&ad_[t * 4];
    float ps = f0.x * a.x + f0.y * a.y + f1.x * a.z + f1.y * a.w;
    float pd = f0.x * b.x + f0.y * b.y + f1.x * b.z + f1.y * b.w;
#pragma unroll
    for (int o = 16; o > 0; o >>= 1) {
        ps += __shfl_xor_sync(0xffffffffu, ps, o);
        pd += __shfl_xor_sync(0xffffffffu, pd, o);
    }
    if (lane == 0) {
        g_asrc1[nid * HH + w] = ps;
        g_adst1[nid * HH + w] = pd;
    }
}

__global__ void k_attdot2(const __nv_bfloat16* __restrict__ h, const float* __restrict__ as_,
                          const float* __restrict__ ad_, int n) {
    int warp = (blockIdx.x * blockDim.x + threadIdx.x) >> 5;
    int lane = threadIdx.x & 31;
    if (warp >= n) return;
    uint4 raw = *(const uint4*)(h + (size_t)warp * CC2 + lane * 8);
    float2 f0 = __bfloat1622float2(*reinterpret_cast<__nv_bfloat162*>(&raw.x));
    float2 f1 = __bfloat1622float2(*reinterpret_cast<__nv_bfloat162*>(&raw.y));
    float2 f2 = __bfloat1622float2(*reinterpret_cast<__nv_bfloat162*>(&raw.z));
    float2 f3 = __bfloat1622float2(*reinterpret_cast<__nv_bfloat162*>(&raw.w));
    float4 a0 = *(const float4*)&as_[lane * 8];
    float4 a1 = *(const float4*)&as_[lane * 8 + 4];
    float4 b0 = *(const float4*)&ad_[lane * 8];
    float4 b1 = *(const float4*)&ad_[lane * 8 + 4];
    float ps = f0.x * a0.x + f0.y * a0.y + f1.x * a0.z + f1.y * a0.w +
               f2.x * a1.x + f2.y * a1.y + f3.x * a1.z + f3.y * a1.w;
    float pd = f0.x * b0.x + f0.y * b0.y + f1.x * b0.z + f1.y * b0.w +
               f2.x * b1.x + f2.y * b1.y + f3.x * b1.z + f3.y * b1.w;
#pragma unroll
    for (int o = 16; o > 0; o >>= 1) {
        ps += __shfl_xor_sync(0xffffffffu, ps, o);
        pd += __shfl_xor_sync(0xffffffffu, pd, o);
    }
    if (lane == 0) {
        g_asrc2[warp] = ps;
        g_adst2[warp] = pd;
    }
}

// ---------------- fused softmax + aggregation (unroll-4 for MLP) ----------------
__device__ __forceinline__ float lrelu(float e) { return (e > 0.f) ? e : 0.2f * e; }

__global__ void k_gat1_agg(const __nv_bfloat16* __restrict__ h, const float* __restrict__ bias,
                           float* __restrict__ out) {
    int d = blockIdx.x;
    int t = threadIdx.x, w = t >> 5, lane = t & 31;
    int beg = g_rowptr[d], end = g_rowptr[d + 1];
    float ad = g_adst1[d * HH + w];

    float sum = 0.f;
    for (int k = beg + lane; k < end; k += 32) {
        int s = g_col[k];
        sum += __expf(lrelu(g_asrc1[s * HH + w] + ad));
    }
#pragma unroll
    for (int o = 16; o > 0; o >>= 1) sum += __shfl_xor_sync(0xffffffffu, sum, o);
    float inv = 1.f / sum;

    float ax = 0.f, ay = 0.f, az = 0.f, aw = 0.f;
    int k = beg;
    for (; k + 4 <= end; k += 4) {
        int s0 = g_col[k], s1 = g_col[k + 1], s2 = g_col[k + 2], s3 = g_col[k + 3];
        float a0 = __expf(lrelu(g_asrc1[s0 * HH + w] + ad)) * inv;
        float a1 = __expf(lrelu(g_asrc1[s1 * HH + w] + ad)) * inv;
        float a2 = __expf(lrelu(g_asrc1[s2 * HH + w] + ad)) * inv;
        float a3 = __expf(lrelu(g_asrc1[s3 * HH + w] + ad)) * inv;
        uint2 r0 = *(const uint2*)(h + (size_t)s0 * D1 + t * 4);
        uint2 r1 = *(const uint2*)(h + (size_t)s1 * D1 + t * 4);
        uint2 r2 = *(const uint2*)(h + (size_t)s2 * D1 + t * 4);
        uint2 r3 = *(const uint2*)(h + (size_t)s3 * D1 + t * 4);
        float2 p, q;
        p = __bfloat1622float2(*reinterpret_cast<__nv_bfloat162*>(&r0.x));
        q = __bfloat1622float2(*reinterpret_cast<__nv_bfloat162*>(&r0.y));
        ax += p.x * a0; ay += p.y * a0; az += q.x * a0; aw += q.y * a0;
        p = __bfloat1622float2(*reinterpret_cast<__nv_bfloat162*>(&r1.x));
        q = __bfloat1622float2(*reinterpret_cast<__nv_bfloat162*>(&r1.y));
        ax += p.x * a1; ay += p.y * a1; az += q.x * a1; aw += q.y * a1;
        p = __bfloat1622float2(*reinterpret_cast<__nv_bfloat162*>(&r2.x));
        q = __bfloat1622float2(*reinterpret_cast<__nv_bfloat162*>(&r2.y));
        ax += p.x * a2; ay += p.y * a2; az += q.x * a2; aw += q.y * a2;
        p = __bfloat1622float2(*reinterpret_cast<__nv_bfloat162*>(&r3.x));
        q = __bfloat1622float2(*reinterpret_cast<__nv_bfloat162*>(&r3.y));
        ax += p.x * a3; ay += p.y * a3; az += q.x * a3; aw += q.y * a3;
    }
    for (; k < end; k++) {
        int s = g_col[k];
        float a = __expf(lrelu(g_asrc1[s * HH + w] + ad)) * inv;
        uint2 r = *(const uint2*)(h + (size_t)s * D1 + t * 4);
        float2 p = __bfloat1622float2(*reinterpret_cast<__nv_bfloat162*>(&r.x));
        float2 q = __bfloat1622float2(*reinterpret_cast<__nv_bfloat162*>(&r.y));
        ax += p.x * a; ay += p.y * a; az += q.x * a; aw += q.y * a;
    }
    float4 b = *(const float4*)&bias[t * 4];
    *(float4*)&out[(size_t)d * D1 + t * 4] =
        make_float4(fmaxf(ax + b.x, 0.f), fmaxf(ay + b.y, 0.f),
                    fmaxf(az + b.z, 0.f), fmaxf(aw + b.w, 0.f));
}

__global__ void k_gat2_agg(const __nv_bfloat16* __restrict__ h, const float* __restrict__ bias,
                           float* __restrict__ out) {
    int d = blockIdx.x;
    int t = threadIdx.x, lane = t & 31;
    int beg = g_rowptr[d], end = g_rowptr[d + 1];
    float ad = g_adst2[d];

    float sum = 0.f;
    for (int k = beg + lane; k < end; k += 32) {
        int s = g_col[k];
        sum += __expf(lrelu(g_asrc2[s] + ad));
    }
#pragma unroll
    for (int o = 16; o > 0; o >>= 1) sum += __shfl_xor_sync(0xffffffffu, sum, o);
    float inv = 1.f / sum;

    float ax = 0.f, ay = 0.f, az = 0.f, aw = 0.f;
    int k = beg;
    for (; k + 4 <= end; k += 4) {
        int s0 = g_col[k], s1 = g_col[k + 1], s2 = g_col[k + 2], s3 = g_col[k + 3];
        float a0 = __expf(lrelu(g_asrc2[s0] + ad)) * inv;
        float a1 = __expf(lrelu(g_asrc2[s1] + ad)) * inv;
        float a2 = __expf(lrelu(g_asrc2[s2] + ad)) * inv;
        float a3 = __expf(lrelu(g_asrc2[s3] + ad)) * inv;
        uint2 r0 = *(const uint2*)(h + (size_t)s0 * CC2 + t * 4);
        uint2 r1 = *(const uint2*)(h + (size_t)s1 * CC2 + t * 4);
        uint2 r2 = *(const uint2*)(h + (size_t)s2 * CC2 + t * 4);
        uint2 r3 = *(const uint2*)(h + (size_t)s3 * CC2 + t * 4);
        float2 p, q;
        p = __bfloat1622float2(*reinterpret_cast<__nv_bfloat162*>(&r0.x));
        q = __bfloat1622float2(*reinterpret_cast<__nv_bfloat162*>(&r0.y));
        ax += p.x * a0; ay += p.y * a0; az += q.x * a0; aw += q.y * a0;
        p = __bfloat1622float2(*reinterpret_cast<__nv_bfloat162*>(&r1.x));
        q = __bfloat1622float2(*reinterpret_cast<__nv_bfloat162*>(&r1.y));
        ax += p.x * a1; ay += p.y * a1; az += q.x * a1; aw += q.y * a1;
        p = __bfloat1622float2(*reinterpret_cast<__nv_bfloat162*>(&r2.x));
        q = __bfloat1622float2(*reinterpret_cast<__nv_bfloat162*>(&r2.y));
        ax += p.x * a2; ay += p.y * a2; az += q.x * a2; aw += q.y * a2;
        p = __bfloat1622float2(*reinterpret_cast<__nv_bfloat162*>(&r3.x));
        q = __bfloat1622float2(*reinterpret_cast<__nv_bfloat162*>(&r3.y));
        ax += p.x * a3; ay += p.y * a3; az += q.x * a3; aw += q.y * a3;
    }
    for (; k < end; k++) {
        int s = g_col[k];
        float a = __expf(lrelu(g_asrc2[s] + ad)) * inv;
        uint2 r = *(const uint2*)(h + (size_t)s * CC2 + t * 4);
        float2 p = __bfloat1622float2(*reinterpret_cast<__nv_bfloat162*>(&r.x));
        float2 q = __bfloat1622float2(*reinterpret_cast<__nv_bfloat162*>(&r.y));
        ax += p.x * a; ay += p.y * a; az += q.x * a; aw += q.y * a;
    }
    float4 b = *(const float4*)&bias[t * 4];
    *(float4*)&out[(size_t)d * CC2 + t * 4] =
        make_float4(ax + b.x, ay + b.y, az + b.z, aw + b.w);
}

// ---------------- fused pool + MLP head ----------------
__global__ void k_poolhead(const float* __restrict__ x,
                           const float* __restrict__ w1, const float* __restrict__ b1,
                           const float* __restrict__ w2, const float* __restrict__ b2,
                           float* __restrict__ out) {
    int g = blockIdx.x;
    int t = threadIdx.x;  // 256
    __shared__ float pool[CC2];
    __shared__ float s1[64];
    __shared__ float logits[NCLS];

    int beg = g_starts[g], end = g_starts[g + 1];
    float m = -1e30f;
    for (int i = beg; i < end; i++) m = fmaxf(m, x[(size_t)i * CC2 + t]);
    pool[t] = m;
    __syncthreads();

    if (t < 64) {
        float acc = b1[t];
        for (int k = 0; k < CC2; k++) acc += pool[k] * w1[k * 64 + t];
        s1[t] = fmaxf(acc, 0.f);
    }
    __syncthreads();
    if (t < NCLS) {
        float l = b2[t];
        for (int k = 0; k < 64; k++) l += s1[k] * w2[k * NCLS + t];
        logits[t] = l;
    }
    __syncthreads();
    if (t < NCLS) {
        float mm = -1e30f;
        for (int j = 0; j < NCLS; j++) mm = fmaxf(mm, logits[j]);
        float se = 0.f;
        for (int j = 0; j < NCLS; j++) se += expf(logits[j] - mm);
        out[g * NCLS + t] = logits[t] - mm - logf(se);
    }
}

// ---------------- launch ----------------
extern "C" void kernel_launch(void* const* d_in, const int* in_sizes, int n_in,
                              void* d_out, int out_size) {
    const float* x        = (const float*)d_in[0];
    const int*   ei       = (const int*)d_in[1];
    const int*   batch    = (const int*)d_in[2];
    const float* W1       = (const float*)d_in[3];
    const float* att_src1 = (const float*)d_in[4];
    const float* att_dst1 = (const float*)d_in[5];
    const float* b1       = (const float*)d_in[6];
    const float* W2       = (const float*)d_in[7];
    const float* att_src2 = (const float*)d_in[8];
    const float* att_dst2 = (const float*)d_in[9];
    const float* b2       = (const float*)d_in[10];
    const float* fc1_w    = (const float*)d_in[11];
    const float* fc1_b    = (const float*)d_in[12];
    const float* fc2_w    = (const float*)d_in[13];
    const float* fc2_b    = (const float*)d_in[14];
    float* out = (float*)d_out;

    const int n = in_sizes[2];
    const int E = in_sizes[1] / 2;

    static cudaStream_t s1;
    static cudaEvent_t e_fork, e_join;
    static int inited = 0;
    if (!inited) {
        cudaFuncSetAttribute(k_gemm_tf32_bf16out, cudaFuncAttributeMaxDynamicSharedMemorySize,
                             GEMM_SMEM_BYTES);
        cudaStreamCreateWithFlags(&s1, cudaStreamNonBlocking);
        cudaEventCreateWithFlags(&e_fork, cudaEventDisableTiming);
        cudaEventCreateWithFlags(&e_join, cudaEventDisableTiming);
        inited = 1;
    }

    __nv_bfloat16 *h1, *h2;
    float *out1, *out2;
    cudaGetSymbolAddress((void**)&h1, g_h1);
    cudaGetSymbolAddress((void**)&out1, g_out1);
    cudaGetSymbolAddress((void**)&h2, g_h2);
    cudaGetSymbolAddress((void**)&out2, g_out2);

    // ---- fork: CSR build on side stream, GEMM1+attdot1 on main ----
    cudaEventRecord(e_fork, 0);
    cudaStreamWaitEvent(s1, e_fork, 0);

    k_init<<<(n + 255) / 256, 256, 0, s1>>>(batch, n);
    k_count_deg<<<(E + 255) / 256, 256, 0, s1>>>(ei, E);
    k_scan_fused<<<1, 1024, 0, s1>>>(n);
    k_scatter<<<(E + n + 255) / 256, 256, 0, s1>>>(ei, E, n);
    cudaEventRecord(e_join, s1);

    {
        dim3 grid(D1 / TBN, (n + TBM - 1) / TBM);
        k_gemm_tf32_bf16out<<<grid, 256, GEMM_SMEM_BYTES>>>(x, W1, h1, n, D1, FF);
    }
    k_attdot1<<<n, 128>>>(h1, att_src1, att_dst1, n);

    // ---- join: aggregation needs CSR ----
    cudaStreamWaitEvent(0, e_join, 0);
    k_gat1_agg<<<n, 128>>>(h1, b1, out1);

    // ---- layer 2 ----
    {
        dim3 grid(CC2 / TBN, (n + TBM - 1) / TBM);
        k_gemm_tf32_bf16out<<<grid, 256, GEMM_SMEM_BYTES>>>(out1, W2, h2, n, CC2, D1);
    }
    k_attdot2<<<(n * 32 + 255) / 256, 256>>>(h2, att_src2, att_dst2, n);
    k_gat2_agg<<<n, 64>>>(h2, b2, out2);

    // ---- pool + head ----
    k_poolhead<<<GG, CC2>>>(out2, fc1_w, fc1_b, fc2_w, fc2_b, out);
}

// round 9
// speedup vs baseline: 1.2841x; 1.2841x over previous
#include <cuda_runtime.h>
#include <cuda_bf16.h>
#include <math.h>
#include <stdint.h>

// ---------------- problem constants ----------------
#define NN      20000
#define EE      160000
#define ETOT    (2*EE + NN)
#define FF      128
#define HH      4
#define CC1     128
#define D1      (HH*CC1)       // 512
#define CC2     256
#define GG      64
#define NCLS    10

// ---------------- device scratch ----------------
__device__ __nv_bfloat16 g_xb[NN * FF];     // x in bf16
__device__ __nv_bfloat16 g_wt1[D1 * FF];    // W1^T [512][128] bf16
__device__ __nv_bfloat16 g_wt2[CC2 * D1];   // W2^T [256][512] bf16
__device__ __nv_bfloat16 g_h1[NN * D1];
__device__ __nv_bfloat16 g_out1[NN * D1];   // relu(GAT1) bf16 (feeds GEMM2)
__device__ __nv_bfloat16 g_h2[NN * CC2];
__device__ float         g_out2[NN * CC2];
__device__ float g_asrc1[NN * HH];
__device__ float g_adst1[NN * HH];
__device__ float g_asrc2[NN];
__device__ float g_adst2[NN];
__device__ int   g_deg[NN];
__device__ int   g_rowptr[NN + 1];
__device__ int   g_wp[NN];
__device__ int   g_col[ETOT];
__device__ int   g_starts[GG + 1];

// ---------------- CSR build (side stream) ----------------
__global__ void k_init(const int* __restrict__ batch, int n) {
    int i = blockIdx.x * blockDim.x + threadIdx.x;
    if (i < n) {
        g_deg[i] = 1;  // self loop
        if (i == 0) {
            g_starts[batch[0]] = 0;
            g_starts[GG] = n;
        } else if (batch[i] != batch[i - 1]) {
            g_starts[batch[i]] = i;
        }
    }
}

__global__ void k_count_deg(const int* __restrict__ ei, int E) {
    int j = blockIdx.x * blockDim.x + threadIdx.x;
    if (j < E) {
        atomicAdd(&g_deg[ei[j]], 1);
        atomicAdd(&g_deg[ei[E + j]], 1);
    }
}

__global__ __launch_bounds__(1024) void k_scan_fused(int n) {
    const int t = threadIdx.x, lane = t & 31, wid = t >> 5;
    const int chunk = (n + 1023) / 1024;
    int b = t * chunk, e = min(b + chunk, n);
    if (b > n) b = n;
    if (e < b) e = b;

    int s = 0;
    for (int i = b; i < e; i++) s += g_deg[i];

    int v = s;
#pragma unroll
    for (int o = 1; o < 32; o <<= 1) {
        int x = __shfl_up_sync(0xffffffffu, v, o);
        if (lane >= o) v += x;
    }
    __shared__ int wtot[32];
    if (lane == 31) wtot[wid] = v;
    __syncthreads();
    if (t < 32) {
        int w = wtot[t];
        int u = w;
#pragma unroll
        for (int o = 1; o < 32; o <<= 1) {
            int x = __shfl_up_sync(0xffffffffu, u, o);
            if (t >= o) u += x;
        }
        wtot[t] = u - w;
        if (t == 31) g_rowptr[n] = u;
    }
    __syncthreads();
    int run = v - s + wtot[wid];
    for (int i = b; i < e; i++) {
        int d = g_deg[i];
        g_rowptr[i] = run;
        g_wp[i] = run;
        run += d;
    }
}

__global__ void k_scatter(const int* __restrict__ ei, int E, int n) {
    int j = blockIdx.x * blockDim.x + threadIdx.x;
    if (j < E) {
        int s = ei[j], d = ei[E + j];
        g_col[atomicAdd(&g_wp[d], 1)] = s;
        g_col[atomicAdd(&g_wp[s], 1)] = d;
    } else if (j < E + n) {
        int i = j - E;
        g_col[atomicAdd(&g_wp[i], 1)] = i;
    }
}

// ---------------- conversions (main stream, before GEMM1) ----------------
// x -> bf16, and zero the att-dot accumulators (GEMM epilogues atomicAdd into them)
__global__ void k_cvtx(const float* __restrict__ x, int n) {
    int i = blockIdx.x * blockDim.x + threadIdx.x;
    int tot = n * FF / 2;
    if (i < tot) {
        float2 v = *(const float2*)(x + i * 2);
        *(__nv_bfloat162*)(g_xb + i * 2) = __float22bfloat162_rn(v);
    }
    if (i < n) {
        *(float4*)&g_asrc1[i * 4] = make_float4(0.f, 0.f, 0.f, 0.f);
        *(float4*)&g_adst1[i * 4] = make_float4(0.f, 0.f, 0.f, 0.f);
        g_asrc2[i] = 0.f;
        g_adst2[i] = 0.f;
    }
}

// W1 [F][D1] -> Wt1 [D1][F] bf16 ;  W2 [D1][CC2] -> Wt2 [CC2][D1] bf16
__global__ void k_cvtw(const float* __restrict__ W1, const float* __restrict__ W2) {
    int i = blockIdx.x * blockDim.x + threadIdx.x;
    if (i < D1 * FF) {
        int nc = i / FF, kc = i % FF;
        g_wt1[i] = __float2bfloat16(W1[kc * D1 + nc]);
    } else if (i < D1 * FF + CC2 * D1) {
        int o = i - D1 * FF;
        int nc = o / D1, kc = o % D1;
        g_wt2[o] = __float2bfloat16(W2[kc * CC2 + nc]);
    }
}

// ---------------- bf16 tensor-core GEMM + fused attention-dot epilogue ----------------
// C[M,N] = A[M,K] @ Bt[N,K]^T, all bf16, fp32 accum. N%128==0, K%64==0.
// Epilogue: atomicAdd per-row dots with attS/attD into outS/outD.
__device__ __forceinline__ void mma_bf16(float c[4], const unsigned a[4], const unsigned b[2]) {
    asm volatile(
        "mma.sync.aligned.m16n8k16.row.col.f32.bf16.bf16.f32 "
        "{%0,%1,%2,%3}, {%4,%5,%6,%7}, {%8,%9}, {%0,%1,%2,%3};"
        : "+f"(c[0]), "+f"(c[1]), "+f"(c[2]), "+f"(c[3])
        : "r"(a[0]), "r"(a[1]), "r"(a[2]), "r"(a[3]), "r"(b[0]), "r"(b[1]));
}

__device__ __forceinline__ void cp16(uint32_t dst, const void* src, int szbytes) {
    asm volatile("cp.async.ca.shared.global [%0], [%1], 16, %2;\n"
                 :: "r"(dst), "l"(src), "r"(szbytes));
}

#define TBM 128
#define TBN 128
#define BKH 64                      // K per tile (bf16 halves)
#define AST 72                      // row stride in halves (64 + 8 pad = 16B pad)
#define ATILE (128 * AST)           // 9216 halves per tile (A or B)
#define GEMM_SMEM_BYTES (2 * 2 * ATILE * 2)  // 73728

__global__ __launch_bounds__(256) void k_gemm_bf16(const __nv_bfloat16* __restrict__ A,
                                                   const __nv_bfloat16* __restrict__ Bt,
                                                   __nv_bfloat16* __restrict__ C,
                                                   int M, int N, int K,
                                                   const float* __restrict__ attS,
                                                   const float* __restrict__ attD,
                                                   float* __restrict__ outS,
                                                   float* __restrict__ outD,
                                                   int head_shift, int head_stride) {
    extern __shared__ __nv_bfloat16 smh[];
    __nv_bfloat16* As = smh;                 // [2][ATILE]
    __nv_bfloat16* Bs = smh + 2 * ATILE;     // [2][ATILE]
    uint32_t as_base = (uint32_t)__cvta_generic_to_shared(As);
    uint32_t bs_base = (uint32_t)__cvta_generic_to_shared(Bs);

    int tid = threadIdx.x;
    int bm = blockIdx.y * TBM, bn = blockIdx.x * TBN;
    int w = tid >> 5, lane = tid & 31;
    int wy = w & 3, wx = w >> 2;
    int gid = lane >> 2, tig = lane & 3;

    float c[2][8][4];
#pragma unroll
    for (int mt = 0; mt < 2; mt++)
#pragma unroll
        for (int nt = 0; nt < 8; nt++)
#pragma unroll
            for (int r = 0; r < 4; r++) c[mt][nt][r] = 0.f;

    const int KT = K / BKH;

    auto load_tile = [&](int k0, int st) {
#pragma unroll
        for (int i = 0; i < 4; i++) {
            int q = tid + i * 256;
            int row = q >> 3;
            int ch = (q & 7) * 8;         // halves
            int gr = bm + row;
            uint32_t d = as_base + (uint32_t)(st * ATILE + row * AST + ch) * 2u;
            cp16(d, A + (size_t)gr * K + k0 + ch, (gr < M) ? 16 : 0);
        }
#pragma unroll
        for (int i = 0; i < 4; i++) {
            int q = tid + i * 256;
            int row = q >> 3;
            int ch = (q & 7) * 8;
            uint32_t d = bs_base + (uint32_t)(st * ATILE + row * AST + ch) * 2u;
            cp16(d, Bt + (size_t)(bn + row) * K + k0 + ch, 16);
        }
        asm volatile("cp.async.commit_group;\n");
    };

    load_tile(0, 0);

    for (int it = 0; it < KT; it++) {
        if (it + 1 < KT) {
            load_tile((it + 1) * BKH, (it + 1) & 1);
            asm volatile("cp.async.wait_group 1;\n");
        } else {
            asm volatile("cp.async.wait_group 0;\n");
        }
        __syncthreads();

        const __nv_bfloat16* as = As + (it & 1) * ATILE;
        const __nv_bfloat16* bs = Bs + (it & 1) * ATILE;
#pragma unroll
        for (int ks = 0; ks < 4; ks++) {
            int kb = ks * 16;
            unsigned af[2][4], bf[8][2];
#pragma unroll
            for (int mt = 0; mt < 2; mt++) {
                int r0 = wy * 32 + mt * 16 + gid;
                af[mt][0] = *(const unsigned*)(as + r0 * AST + kb + 2 * tig);
                af[mt][1] = *(const unsigned*)(as + (r0 + 8) * AST + kb + 2 * tig);
                af[mt][2] = *(const unsigned*)(as + r0 * AST + kb + 2 * tig + 8);
                af[mt][3] = *(const unsigned*)(as + (r0 + 8) * AST + kb + 2 * tig + 8);
            }
#pragma unroll
            for (int nt = 0; nt < 8; nt++) {
                int n0 = wx * 64 + nt * 8 + gid;
                bf[nt][0] = *(const unsigned*)(bs + n0 * AST + kb + 2 * tig);
                bf[nt][1] = *(const unsigned*)(bs + n0 * AST + kb + 2 * tig + 8);
            }
#pragma unroll
            for (int mt = 0; mt < 2; mt++)
#pragma unroll
                for (int nt = 0; nt < 8; nt++) mma_bf16(c[mt][nt], af[mt], bf[nt]);
        }
        __syncthreads();
    }

    // ---- store C + fused attention dots ----
    int hidx = bn >> head_shift;
#pragma unroll
    for (int mt = 0; mt < 2; mt++) {
        int r_lo = bm + wy * 32 + mt * 16 + gid;
        int r_hi = r_lo + 8;
        float psl = 0.f, pdl = 0.f, psh = 0.f, pdh = 0.f;
#pragma unroll
        for (int nt = 0; nt < 8; nt++) {
            int cl = wx * 64 + nt * 8 + 2 * tig;
#pragma unroll
            for (int j = 0; j < 2; j++) {
                float s_ = __ldg(&attS[bn + cl + j]);
                float d_ = __ldg(&attD[bn + cl + j]);
                psl += c[mt][nt][j] * s_;     pdl += c[mt][nt][j] * d_;
                psh += c[mt][nt][2 + j] * s_; pdh += c[mt][nt][2 + j] * d_;
            }
            if (r_lo < M) {
                __nv_bfloat162 v = __float22bfloat162_rn(make_float2(c[mt][nt][0], c[mt][nt][1]));
                *(__nv_bfloat162*)&C[(size_t)r_lo * N + bn + cl] = v;
            }
            if (r_hi < M) {
                __nv_bfloat162 v = __float22bfloat162_rn(make_float2(c[mt][nt][2], c[mt][nt][3]));
                *(__nv_bfloat162*)&C[(size_t)r_hi * N + bn + cl] = v;
            }
        }
        // reduce over tig group (lanes gid*4 + tig)
#pragma unroll
        for (int o = 1; o < 4; o <<= 1) {
            psl += __shfl_xor_sync(0xffffffffu, psl, o);
            pdl += __shfl_xor_sync(0xffffffffu, pdl, o);
            psh += __shfl_xor_sync(0xffffffffu, psh, o);
            pdh += __shfl_xor_sync(0xffffffffu, pdh, o);
        }
        if (tig == 0) {
            if (r_lo < M) {
                atomicAdd(&outS[r_lo * head_stride + hidx], psl);
                atomicAdd(&outD[r_lo * head_stride + hidx], pdl);
            }
            if (r_hi < M) {
                atomicAdd(&outS[r_hi * head_stride + hidx], psh);
                atomicAdd(&outD[r_hi * head_stride + hidx], pdh);
            }
        }
    }
}

// ---------------- fused softmax + aggregation ----------------
__device__ __forceinline__ float lrelu(float e) { return (e > 0.f) ? e : 0.2f * e; }

__global__ void k_gat1_agg(const __nv_bfloat16* __restrict__ h, const float* __restrict__ bias,
                           __nv_bfloat16* __restrict__ out) {
    int d = blockIdx.x;
    int t = threadIdx.x, w = t >> 5, lane = t & 31;
    int beg = g_rowptr[d], end = g_rowptr[d + 1];
    float ad = g_adst1[d * HH + w];

    float sum = 0.f;
    for (int k = beg + lane; k < end; k += 32) {
        int s = g_col[k];
        sum += __expf(lrelu(g_asrc1[s * HH + w] + ad));
    }
#pragma unroll
    for (int o = 16; o > 0; o >>= 1) sum += __shfl_xor_sync(0xffffffffu, sum, o);
    float inv = 1.f / sum;

    float ax = 0.f, ay = 0.f, az = 0.f, aw = 0.f;
    for (int k = beg; k < end; k++) {
        int s = g_col[k];
        float a = __expf(lrelu(g_asrc1[s * HH + w] + ad)) * inv;
        uint2 r = *(const uint2*)(h + (size_t)s * D1 + t * 4);
        float2 p = __bfloat1622float2(*reinterpret_cast<__nv_bfloat162*>(&r.x));
        float2 q = __bfloat1622float2(*reinterpret_cast<__nv_bfloat162*>(&r.y));
        ax += p.x * a; ay += p.y * a; az += q.x * a; aw += q.y * a;
    }
    float4 b = *(const float4*)&bias[t * 4];
    __nv_bfloat162 v0 = __float22bfloat162_rn(make_float2(fmaxf(ax + b.x, 0.f), fmaxf(ay + b.y, 0.f)));
    __nv_bfloat162 v1 = __float22bfloat162_rn(make_float2(fmaxf(az + b.z, 0.f), fmaxf(aw + b.w, 0.f)));
    uint2 pack;
    pack.x = *reinterpret_cast<unsigned*>(&v0);
    pack.y = *reinterpret_cast<unsigned*>(&v1);
    *(uint2*)&out[(size_t)d * D1 + t * 4] = pack;
}

__global__ void k_gat2_agg(const __nv_bfloat16* __restrict__ h, const float* __restrict__ bias,
                           float* __restrict__ out) {
    int d = blockIdx.x;
    int t = threadIdx.x, lane = t & 31;
    int beg = g_rowptr[d], end = g_rowptr[d + 1];
    float ad = g_adst2[d];

    float sum = 0.f;
    for (int k = beg + lane; k < end; k += 32) {
        int s = g_col[k];
        sum += __expf(lrelu(g_asrc2[s] + ad));
    }
#pragma unroll
    for (int o = 16; o > 0; o >>= 1) sum += __shfl_xor_sync(0xffffffffu, sum, o);
    float inv = 1.f / sum;

    float ax = 0.f, ay = 0.f, az = 0.f, aw = 0.f;
    for (int k = beg; k < end; k++) {
        int s = g_col[k];
        float a = __expf(lrelu(g_asrc2[s] + ad)) * inv;
        uint2 r = *(const uint2*)(h + (size_t)s * CC2 + t * 4);
        float2 p = __bfloat1622float2(*reinterpret_cast<__nv_bfloat162*>(&r.x));
        float2 q = __bfloat1622float2(*reinterpret_cast<__nv_bfloat162*>(&r.y));
        ax += p.x * a; ay += p.y * a; az += q.x * a; aw += q.y * a;
    }
    float4 b = *(const float4*)&bias[t * 4];
    *(float4*)&out[(size_t)d * CC2 + t * 4] =
        make_float4(ax + b.x, ay + b.y, az + b.z, aw + b.w);
}

// ---------------- fused pool + MLP head ----------------
__global__ void k_poolhead(const float* __restrict__ x,
                           const float* __restrict__ w1, const float* __restrict__ b1,
                           const float* __restrict__ w2, const float* __restrict__ b2,
                           float* __restrict__ out) {
    int g = blockIdx.x;
    int t = threadIdx.x;  // 256
    __shared__ float pool[CC2];
    __shared__ float s1[64];
    __shared__ float logits[NCLS];

    int beg = g_starts[g], end = g_starts[g + 1];
    float m = -1e30f;
    for (int i = beg; i < end; i++) m = fmaxf(m, x[(size_t)i * CC2 + t]);
    pool[t] = m;
    __syncthreads();

    if (t < 64) {
        float acc = b1[t];
        for (int k = 0; k < CC2; k++) acc += pool[k] * w1[k * 64 + t];
        s1[t] = fmaxf(acc, 0.f);
    }
    __syncthreads();
    if (t < NCLS) {
        float l = b2[t];
        for (int k = 0; k < 64; k++) l += s1[k] * w2[k * NCLS + t];
        logits[t] = l;
    }
    __syncthreads();
    if (t < NCLS) {
        float mm = -1e30f;
        for (int j = 0; j < NCLS; j++) mm = fmaxf(mm, logits[j]);
        float se = 0.f;
        for (int j = 0; j < NCLS; j++) se += expf(logits[j] - mm);
        out[g * NCLS + t] = logits[t] - mm - logf(se);
    }
}

// ---------------- launch ----------------
extern "C" void kernel_launch(void* const* d_in, const int* in_sizes, int n_in,
                              void* d_out, int out_size) {
    const float* x        = (const float*)d_in[0];
    const int*   ei       = (const int*)d_in[1];
    const int*   batch    = (const int*)d_in[2];
    const float* W1       = (const float*)d_in[3];
    const float* att_src1 = (const float*)d_in[4];
    const float* att_dst1 = (const float*)d_in[5];
    const float* b1       = (const float*)d_in[6];
    const float* W2       = (const float*)d_in[7];
    const float* att_src2 = (const float*)d_in[8];
    const float* att_dst2 = (const float*)d_in[9];
    const float* b2       = (const float*)d_in[10];
    const float* fc1_w    = (const float*)d_in[11];
    const float* fc1_b    = (const float*)d_in[12];
    const float* fc2_w    = (const float*)d_in[13];
    const float* fc2_b    = (const float*)d_in[14];
    float* out = (float*)d_out;

    const int n = in_sizes[2];
    const int E = in_sizes[1] / 2;

    static cudaStream_t s1;
    static cudaEvent_t e_fork, e_join;
    static int inited = 0;
    if (!inited) {
        cudaFuncSetAttribute(k_gemm_bf16, cudaFuncAttributeMaxDynamicSharedMemorySize,
                             GEMM_SMEM_BYTES);
        cudaStreamCreateWithFlags(&s1, cudaStreamNonBlocking);
        cudaEventCreateWithFlags(&e_fork, cudaEventDisableTiming);
        cudaEventCreateWithFlags(&e_join, cudaEventDisableTiming);
        inited = 1;
    }

    __nv_bfloat16 *xb, *wt1, *wt2, *h1, *out1, *h2;
    float *out2, *asrc1, *adst1, *asrc2, *adst2;
    cudaGetSymbolAddress((void**)&xb, g_xb);
    cudaGetSymbolAddress((void**)&wt1, g_wt1);
    cudaGetSymbolAddress((void**)&wt2, g_wt2);
    cudaGetSymbolAddress((void**)&h1, g_h1);
    cudaGetSymbolAddress((void**)&out1, g_out1);
    cudaGetSymbolAddress((void**)&h2, g_h2);
    cudaGetSymbolAddress((void**)&out2, g_out2);
    cudaGetSymbolAddress((void**)&asrc1, g_asrc1);
    cudaGetSymbolAddress((void**)&adst1, g_adst1);
    cudaGetSymbolAddress((void**)&asrc2, g_asrc2);
    cudaGetSymbolAddress((void**)&adst2, g_adst2);

    // ---- fork: CSR build on side stream ----
    cudaEventRecord(e_fork, 0);
    cudaStreamWaitEvent(s1, e_fork, 0);
    k_init<<<(n + 255) / 256, 256, 0, s1>>>(batch, n);
    k_count_deg<<<(E + 255) / 256, 256, 0, s1>>>(ei, E);
    k_scan_fused<<<1, 1024, 0, s1>>>(n);
    k_scatter<<<(E + n + 255) / 256, 256, 0, s1>>>(ei, E, n);
    cudaEventRecord(e_join, s1);

    // ---- main: convert inputs, GEMM1 (+attdot1 epilogue) ----
    k_cvtx<<<(n * FF / 2 + 255) / 256, 256>>>(x, n);
    k_cvtw<<<(D1 * FF + CC2 * D1 + 255) / 256, 256>>>(W1, W2);
    {
        dim3 grid(D1 / TBN, (n + TBM - 1) / TBM);
        k_gemm_bf16<<<grid, 256, GEMM_SMEM_BYTES>>>(xb, wt1, h1, n, D1, FF,
                                                    att_src1, att_dst1, asrc1, adst1,
                                                    7, HH);
    }

    // ---- join: aggregation needs CSR ----
    cudaStreamWaitEvent(0, e_join, 0);
    k_gat1_agg<<<n, 128>>>(h1, b1, out1);

    // ---- layer 2 (GEMM2 + attdot2 epilogue) ----
    {
        dim3 grid(CC2 / TBN, (n + TBM - 1) / TBM);
        k_gemm_bf16<<<grid, 256, GEMM_SMEM_BYTES>>>(out1, wt2, h2, n, CC2, D1,
                                                    att_src2, att_dst2, asrc2, adst2,
                                                    8, 1);
    }
    k_gat2_agg<<<n, 64>>>(h2, b2, out2);

    // ---- pool + head ----
    k_poolhead<<<GG, CC2>>>(out2, fc1_w, fc1_b, fc2_w, fc2_b, out);
}

// round 12
// speedup vs baseline: 1.3045x; 1.0159x over previous
#include <cuda_runtime.h>
#include <cuda_bf16.h>
#include <math.h>
#include <stdint.h>

// ---------------- problem constants ----------------
#define NN      20000
#define EE      160000
#define ETOT    (2*EE + NN)
#define FF      128
#define HH      4
#define CC1     128
#define D1      (HH*CC1)       // 512
#define CC2     256
#define GG      64
#define NCLS    10

// ---------------- device scratch ----------------
__device__ __nv_bfloat16 g_xb[NN * FF];
__device__ __nv_bfloat16 g_wt1[D1 * FF];    // W1^T [512][128]
__device__ __nv_bfloat16 g_wt2[CC2 * D1];   // W2^T [256][512]
__device__ __nv_bfloat16 g_h1[NN * D1];
__device__ __nv_bfloat16 g_out1[NN * D1];
__device__ __nv_bfloat16 g_h2[NN * CC2];
__device__ float         g_out2[NN * CC2];
__device__ float g_asrc1[NN * HH];
__device__ float g_adst1[NN * HH];
__device__ float g_asrc2[NN];
__device__ float g_adst2[NN];
__device__ int   g_deg[NN];
__device__ int   g_rowptr[NN + 1];
__device__ int   g_wp[NN];
__device__ int   g_col[ETOT];
__device__ int   g_starts[GG + 1];

// ---------------- CSR build (side stream) ----------------
__global__ void k_init(const int* __restrict__ batch, int n) {
    int i = blockIdx.x * blockDim.x + threadIdx.x;
    if (i < n) {
        g_deg[i] = 1;
        if (i == 0) {
            g_starts[batch[0]] = 0;
            g_starts[GG] = n;
        } else if (batch[i] != batch[i - 1]) {
            g_starts[batch[i]] = i;
        }
    }
}

__global__ void k_count_deg(const int* __restrict__ ei, int E) {
    int j = blockIdx.x * blockDim.x + threadIdx.x;
    if (j < E) {
        atomicAdd(&g_deg[ei[j]], 1);
        atomicAdd(&g_deg[ei[E + j]], 1);
    }
}

__global__ __launch_bounds__(1024) void k_scan_fused(int n) {
    const int t = threadIdx.x, lane = t & 31, wid = t >> 5;
    const int chunk = (n + 1023) / 1024;
    int b = t * chunk, e = min(b + chunk, n);
    if (b > n) b = n;
    if (e < b) e = b;

    int s = 0;
    for (int i = b; i < e; i++) s += g_deg[i];

    int v = s;
#pragma unroll
    for (int o = 1; o < 32; o <<= 1) {
        int x = __shfl_up_sync(0xffffffffu, v, o);
        if (lane >= o) v += x;
    }
    __shared__ int wtot[32];
    if (lane == 31) wtot[wid] = v;
    __syncthreads();
    if (t < 32) {
        int w = wtot[t];
        int u = w;
#pragma unroll
        for (int o = 1; o < 32; o <<= 1) {
            int x = __shfl_up_sync(0xffffffffu, u, o);
            if (t >= o) u += x;
        }
        wtot[t] = u - w;
        if (t == 31) g_rowptr[n] = u;
    }
    __syncthreads();
    int run = v - s + wtot[wid];
    for (int i = b; i < e; i++) {
        int d = g_deg[i];
        g_rowptr[i] = run;
        g_wp[i] = run;
        run += d;
    }
}

__global__ void k_scatter(const int* __restrict__ ei, int E, int n) {
    int j = blockIdx.x * blockDim.x + threadIdx.x;
    if (j < E) {
        int s = ei[j], d = ei[E + j];
        g_col[atomicAdd(&g_wp[d], 1)] = s;
        g_col[atomicAdd(&g_wp[s], 1)] = d;
    } else if (j < E + n) {
        int i = j - E;
        g_col[atomicAdd(&g_wp[i], 1)] = i;
    }
}

// ---------------- merged conversions + zero att accumulators ----------------
__global__ void k_cvt(const float* __restrict__ x, const float* __restrict__ W1,
                      const float* __restrict__ W2, int n) {
    int i = blockIdx.x * blockDim.x + threadIdx.x;
    int totx = n * FF / 2;
    if (i < totx) {
        float2 v = *(const float2*)(x + i * 2);
        *(__nv_bfloat162*)(g_xb + i * 2) = __float22bfloat162_rn(v);
    }
    if (i < D1 * FF) {
        int nc = i / FF, kc = i % FF;
        g_wt1[i] = __float2bfloat16(W1[kc * D1 + nc]);
    }
    if (i < CC2 * D1) {
        int nc = i / D1, kc = i % D1;
        g_wt2[i] = __float2bfloat16(W2[kc * CC2 + nc]);
    }
    if (i < n) {
        *(float4*)&g_asrc1[i * 4] = make_float4(0.f, 0.f, 0.f, 0.f);
        *(float4*)&g_adst1[i * 4] = make_float4(0.f, 0.f, 0.f, 0.f);
        g_asrc2[i] = 0.f;
        g_adst2[i] = 0.f;
    }
}

// ---------------- bf16 tensor-core GEMM (templated N-tile) + att-dot epilogue ----------------
__device__ __forceinline__ void mma_bf16(float c[4], const unsigned a[4], const unsigned b[2]) {
    asm volatile(
        "mma.sync.aligned.m16n8k16.row.col.f32.bf16.bf16.f32 "
        "{%0,%1,%2,%3}, {%4,%5,%6,%7}, {%8,%9}, {%0,%1,%2,%3};"
        : "+f"(c[0]), "+f"(c[1]), "+f"(c[2]), "+f"(c[3])
        : "r"(a[0]), "r"(a[1]), "r"(a[2]), "r"(a[3]), "r"(b[0]), "r"(b[1]));
}

__device__ __forceinline__ void cp16(uint32_t dst, const void* src, int szbytes) {
    asm volatile("cp.async.ca.shared.global [%0], [%1], 16, %2;\n"
                 :: "r"(dst), "l"(src), "r"(szbytes));
}

#define TBM 128
#define BKH 64
#define AST 72
#define ATILE_A (TBM * AST)                    // 9216 halves

// NT = n-tiles per warp (warp covers NT*8 cols, block TBN = NT*16 cols)
template <int NT>
__global__ __launch_bounds__(256) void k_gemm_bf16(const __nv_bfloat16* __restrict__ A,
                                                   const __nv_bfloat16* __restrict__ Bt,
                                                   __nv_bfloat16* __restrict__ C,
                                                   int M, int N, int K,
                                                   const float* __restrict__ attS,
                                                   const float* __restrict__ attD,
                                                   float* __restrict__ outS,
                                                   float* __restrict__ outD,
                                                   int head_shift, int head_stride) {
    constexpr int TBNL = NT * 16;
    constexpr int BTILE = TBNL * AST;
    extern __shared__ __nv_bfloat16 smh[];
    __nv_bfloat16* As = smh;                   // [2][ATILE_A]
    __nv_bfloat16* Bs = smh + 2 * ATILE_A;     // [2][BTILE]
    uint32_t as_base = (uint32_t)__cvta_generic_to_shared(As);
    uint32_t bs_base = (uint32_t)__cvta_generic_to_shared(Bs);

    int tid = threadIdx.x;
    int bm = blockIdx.y * TBM, bn = blockIdx.x * TBNL;
    int w = tid >> 5, lane = tid & 31;
    int wy = w & 3, wx = w >> 2;
    int gid = lane >> 2, tig = lane & 3;

    float c[2][NT][4];
#pragma unroll
    for (int mt = 0; mt < 2; mt++)
#pragma unroll
        for (int nt = 0; nt < NT; nt++)
#pragma unroll
            for (int r = 0; r < 4; r++) c[mt][nt][r] = 0.f;

    const int KT = K / BKH;

    auto load_tile = [&](int k0, int st) {
#pragma unroll
        for (int i = 0; i < 4; i++) {
            int q = tid + i * 256;
            int row = q >> 3;
            int ch = (q & 7) * 8;
            int gr = bm + row;
            uint32_t d = as_base + (uint32_t)(st * ATILE_A + row * AST + ch) * 2u;
            cp16(d, A + (size_t)gr * K + k0 + ch, (gr < M) ? 16 : 0);
        }
#pragma unroll
        for (int i = 0; i < NT / 2; i++) {
            int q = tid + i * 256;
            int row = q >> 3;
            int ch = (q & 7) * 8;
            uint32_t d = bs_base + (uint32_t)(st * BTILE + row * AST + ch) * 2u;
            cp16(d, Bt + (size_t)(bn + row) * K + k0 + ch, 16);
        }
        asm volatile("cp.async.commit_group;\n");
    };

    load_tile(0, 0);

    for (int it = 0; it < KT; it++) {
        if (it + 1 < KT) {
            load_tile((it + 1) * BKH, (it + 1) & 1);
            asm volatile("cp.async.wait_group 1;\n");
        } else {
            asm volatile("cp.async.wait_group 0;\n");
        }
        __syncthreads();

        const __nv_bfloat16* as = As + (it & 1) * ATILE_A;
        const __nv_bfloat16* bs = Bs + (it & 1) * BTILE;
#pragma unroll
        for (int ks = 0; ks < 4; ks++) {
            int kb = ks * 16;
            unsigned af[2][4], bf[NT][2];
#pragma unroll
            for (int mt = 0; mt < 2; mt++) {
                int r0 = wy * 32 + mt * 16 + gid;
                af[mt][0] = *(const unsigned*)(as + r0 * AST + kb + 2 * tig);
                af[mt][1] = *(const unsigned*)(as + (r0 + 8) * AST + kb + 2 * tig);
                af[mt][2] = *(const unsigned*)(as + r0 * AST + kb + 2 * tig + 8);
                af[mt][3] = *(const unsigned*)(as + (r0 + 8) * AST + kb + 2 * tig + 8);
            }
#pragma unroll
            for (int nt = 0; nt < NT; nt++) {
                int n0 = wx * (NT * 8) + nt * 8 + gid;
                bf[nt][0] = *(const unsigned*)(bs + n0 * AST + kb + 2 * tig);
                bf[nt][1] = *(const unsigned*)(bs + n0 * AST + kb + 2 * tig + 8);
            }
#pragma unroll
            for (int mt = 0; mt < 2; mt++)
#pragma unroll
                for (int nt = 0; nt < NT; nt++) mma_bf16(c[mt][nt], af[mt], bf[nt]);
        }
        __syncthreads();
    }

    // ---- store C + fused attention dots ----
    int hidx = bn >> head_shift;
#pragma unroll
    for (int mt = 0; mt < 2; mt++) {
        int r_lo = bm + wy * 32 + mt * 16 + gid;
        int r_hi = r_lo + 8;
        float psl = 0.f, pdl = 0.f, psh = 0.f, pdh = 0.f;
#pragma unroll
        for (int nt = 0; nt < NT; nt++) {
            int cl = wx * (NT * 8) + nt * 8 + 2 * tig;
#pragma unroll
            for (int j = 0; j < 2; j++) {
                float s_ = __ldg(&attS[bn + cl + j]);
                float d_ = __ldg(&attD[bn + cl + j]);
                psl += c[mt][nt][j] * s_;     pdl += c[mt][nt][j] * d_;
                psh += c[mt][nt][2 + j] * s_; pdh += c[mt][nt][2 + j] * d_;
            }
            if (r_lo < M) {
                __nv_bfloat162 v = __float22bfloat162_rn(make_float2(c[mt][nt][0], c[mt][nt][1]));
                *(__nv_bfloat162*)&C[(size_t)r_lo * N + bn + cl] = v;
            }
            if (r_hi < M) {
                __nv_bfloat162 v = __float22bfloat162_rn(make_float2(c[mt][nt][2], c[mt][nt][3]));
                *(__nv_bfloat162*)&C[(size_t)r_hi * N + bn + cl] = v;
            }
        }
#pragma unroll
        for (int o = 1; o < 4; o <<= 1) {
            psl += __shfl_xor_sync(0xffffffffu, psl, o);
            pdl += __shfl_xor_sync(0xffffffffu, pdl, o);
            psh += __shfl_xor_sync(0xffffffffu, psh, o);
            pdh += __shfl_xor_sync(0xffffffffu, pdh, o);
        }
        if (tig == 0) {
            if (r_lo < M) {
                atomicAdd(&outS[r_lo * head_stride + hidx], psl);
                atomicAdd(&outD[r_lo * head_stride + hidx], pdl);
            }
            if (r_hi < M) {
                atomicAdd(&outS[r_hi * head_stride + hidx], psh);
                atomicAdd(&outD[r_hi * head_stride + hidx], pdh);
            }
        }
    }
}

#define GEMM_SMEM_NT4 (2 * (ATILE_A + 64 * AST) * 2)   // 55296

// ---------------- fused softmax + aggregation ----------------
__device__ __forceinline__ float lrelu(float e) { return (e > 0.f) ? e : 0.2f * e; }

__global__ void k_gat1_agg(const __nv_bfloat16* __restrict__ h, const float* __restrict__ bias,
                           __nv_bfloat16* __restrict__ out) {
    int d = blockIdx.x;
    int t = threadIdx.x, w = t >> 5, lane = t & 31;
    int beg = g_rowptr[d], end = g_rowptr[d + 1];
    float ad = g_adst1[d * HH + w];

    float sum = 0.f;
    for (int k = beg + lane; k < end; k += 32) {
        int s = g_col[k];
        sum += __expf(lrelu(g_asrc1[s * HH + w] + ad));
    }
#pragma unroll
    for (int o = 16; o > 0; o >>= 1) sum += __shfl_xor_sync(0xffffffffu, sum, o);
    float inv = 1.f / sum;

    float ax = 0.f, ay = 0.f, az = 0.f, aw = 0.f;
    for (int k = beg; k < end; k++) {
        int s = g_col[k];
        float a = __expf(lrelu(g_asrc1[s * HH + w] + ad)) * inv;
        uint2 r = *(const uint2*)(h + (size_t)s * D1 + t * 4);
        float2 p = __bfloat1622float2(*reinterpret_cast<__nv_bfloat162*>(&r.x));
        float2 q = __bfloat1622float2(*reinterpret_cast<__nv_bfloat162*>(&r.y));
        ax += p.x * a; ay += p.y * a; az += q.x * a; aw += q.y * a;
    }
    float4 b = *(const float4*)&bias[t * 4];
    __nv_bfloat162 v0 = __float22bfloat162_rn(make_float2(fmaxf(ax + b.x, 0.f), fmaxf(ay + b.y, 0.f)));
    __nv_bfloat162 v1 = __float22bfloat162_rn(make_float2(fmaxf(az + b.z, 0.f), fmaxf(aw + b.w, 0.f)));
    uint2 pack;
    pack.x = *reinterpret_cast<unsigned*>(&v0);
    pack.y = *reinterpret_cast<unsigned*>(&v1);
    *(uint2*)&out[(size_t)d * D1 + t * 4] = pack;
}

__global__ void k_gat2_agg(const __nv_bfloat16* __restrict__ h, const float* __restrict__ bias,
                           float* __restrict__ out) {
    int d = blockIdx.x;
    int t = threadIdx.x, lane = t & 31;
    int beg = g_rowptr[d], end = g_rowptr[d + 1];
    float ad = g_adst2[d];

    float sum = 0.f;
    for (int k = beg + lane; k < end; k += 32) {
        int s = g_col[k];
        sum += __expf(lrelu(g_asrc2[s] + ad));
    }
#pragma unroll
    for (int o = 16; o > 0; o >>= 1) sum += __shfl_xor_sync(0xffffffffu, sum, o);
    float inv = 1.f / sum;

    float ax = 0.f, ay = 0.f, az = 0.f, aw = 0.f;
    for (int k = beg; k < end; k++) {
        int s = g_col[k];
        float a = __expf(lrelu(g_asrc2[s] + ad)) * inv;
        uint2 r = *(const uint2*)(h + (size_t)s * CC2 + t * 4);
        float2 p = __bfloat1622float2(*reinterpret_cast<__nv_bfloat162*>(&r.x));
        float2 q = __bfloat1622float2(*reinterpret_cast<__nv_bfloat162*>(&r.y));
        ax += p.x * a; ay += p.y * a; az += q.x * a; aw += q.y * a;
    }
    float4 b = *(const float4*)&bias[t * 4];
    *(float4*)&out[(size_t)d * CC2 + t * 4] =
        make_float4(ax + b.x, ay + b.y, az + b.z, aw + b.w);
}

// ---------------- fused pool + MLP head (1024 threads, 4-way row split) ----------------
__global__ __launch_bounds__(1024) void k_poolhead(const float* __restrict__ x,
                                                   const float* __restrict__ w1,
                                                   const float* __restrict__ b1,
                                                   const float* __restrict__ w2,
                                                   const float* __restrict__ b2,
                                                   float* __restrict__ out) {
    int g = blockIdx.x;
    int t = threadIdx.x;           // 1024
    int c = t & 255, seg = t >> 8; // 4 row-segments
    __shared__ float pmax[4][CC2];
    __shared__ float pool[CC2];
    __shared__ float s1[64];
    __shared__ float logits[NCLS];

    int beg = g_starts[g], end = g_starts[g + 1];
    float m = -1e30f;
    for (int i = beg + seg; i < end; i += 4) m = fmaxf(m, x[(size_t)i * CC2 + c]);
    pmax[seg][c] = m;
    __syncthreads();
    if (t < CC2)
        pool[t] = fmaxf(fmaxf(pmax[0][t], pmax[1][t]), fmaxf(pmax[2][t], pmax[3][t]));
    __syncthreads();

    if (t < 64) {
        float acc = b1[t];
        for (int k = 0; k < CC2; k++) acc += pool[k] * w1[k * 64 + t];
        s1[t] = fmaxf(acc, 0.f);
    }
    __syncthreads();
    if (t < NCLS) {
        float l = b2[t];
        for (int k = 0; k < 64; k++) l += s1[k] * w2[k * NCLS + t];
        logits[t] = l;
    }
    __syncthreads();
    if (t < NCLS) {
        float mm = -1e30f;
        for (int j = 0; j < NCLS; j++) mm = fmaxf(mm, logits[j]);
        float se = 0.f;
        for (int j = 0; j < NCLS; j++) se += expf(logits[j] - mm);
        out[g * NCLS + t] = logits[t] - mm - logf(se);
    }
}

// ---------------- launch ----------------
extern "C" void kernel_launch(void* const* d_in, const int* in_sizes, int n_in,
                              void* d_out, int out_size) {
    const float* x        = (const float*)d_in[0];
    const int*   ei       = (const int*)d_in[1];
    const int*   batch    = (const int*)d_in[2];
    const float* W1       = (const float*)d_in[3];
    const float* att_src1 = (const float*)d_in[4];
    const float* att_dst1 = (const float*)d_in[5];
    const float* b1       = (const float*)d_in[6];
    const float* W2       = (const float*)d_in[7];
    const float* att_src2 = (const float*)d_in[8];
    const float* att_dst2 = (const float*)d_in[9];
    const float* b2       = (const float*)d_in[10];
    const float* fc1_w    = (const float*)d_in[11];
    const float* fc1_b    = (const float*)d_in[12];
    const float* fc2_w    = (const float*)d_in[13];
    const float* fc2_b    = (const float*)d_in[14];
    float* out = (float*)d_out;

    const int n = in_sizes[2];
    const int E = in_sizes[1] / 2;

    static cudaStream_t s1;
    static cudaEvent_t e_fork, e_join;
    static int inited = 0;
    if (!inited) {
        cudaFuncSetAttribute(k_gemm_bf16<4>, cudaFuncAttributeMaxDynamicSharedMemorySize,
                             GEMM_SMEM_NT4);
        cudaStreamCreateWithFlags(&s1, cudaStreamNonBlocking);
        cudaEventCreateWithFlags(&e_fork, cudaEventDisableTiming);
        cudaEventCreateWithFlags(&e_join, cudaEventDisableTiming);
        inited = 1;
    }

    __nv_bfloat16 *xb, *wt1, *wt2, *h1, *out1, *h2;
    float *out2, *asrc1, *adst1, *asrc2, *adst2;
    cudaGetSymbolAddress((void**)&xb, g_xb);
    cudaGetSymbolAddress((void**)&wt1, g_wt1);
    cudaGetSymbolAddress((void**)&wt2, g_wt2);
    cudaGetSymbolAddress((void**)&h1, g_h1);
    cudaGetSymbolAddress((void**)&out1, g_out1);
    cudaGetSymbolAddress((void**)&h2, g_h2);
    cudaGetSymbolAddress((void**)&out2, g_out2);
    cudaGetSymbolAddress((void**)&asrc1, g_asrc1);
    cudaGetSymbolAddress((void**)&adst1, g_adst1);
    cudaGetSymbolAddress((void**)&asrc2, g_asrc2);
    cudaGetSymbolAddress((void**)&adst2, g_adst2);

    // ---- fork: CSR build on side stream ----
    cudaEventRecord(e_fork, 0);
    cudaStreamWaitEvent(s1, e_fork, 0);
    k_init<<<(n + 255) / 256, 256, 0, s1>>>(batch, n);
    k_count_deg<<<(E + 255) / 256, 256, 0, s1>>>(ei, E);
    k_scan_fused<<<1, 1024, 0, s1>>>(n);
    k_scatter<<<(E + n + 255) / 256, 256, 0, s1>>>(ei, E, n);
    cudaEventRecord(e_join, s1);

    // ---- main: convert inputs, GEMM1 (+attdot1 epilogue) ----
    k_cvt<<<(n * FF / 2 + 255) / 256, 256>>>(x, W1, W2, n);
    {
        dim3 grid(D1 / 64, (n + TBM - 1) / TBM);
        k_gemm_bf16<4><<<grid, 256, GEMM_SMEM_NT4>>>(xb, wt1, h1, n, D1, FF,
                                                     att_src1, att_dst1, asrc1, adst1,
                                                     7, HH);
    }

    // ---- join: aggregation needs CSR ----
    cudaStreamWaitEvent(0, e_join, 0);
    k_gat1_agg<<<n, 128>>>(h1, b1, out1);

    // ---- layer 2 (GEMM2 + attdot2 epilogue) ----
    {
        dim3 grid(CC2 / 64, (n + TBM - 1) / TBM);
        k_gemm_bf16<4><<<grid, 256, GEMM_SMEM_NT4>>>(out1, wt2, h2, n, CC2, D1,
                                                     att_src2, att_dst2, asrc2, adst2,
                                                     8, 1);
    }
    k_gat2_agg<<<n, 64>>>(h2, b2, out2);

    // ---- pool + head ----
    k_poolhead<<<GG, 1024>>>(out2, fc1_w, fc1_b, fc2_w, fc2_b, out);
}

// round 13
// speedup vs baseline: 1.5584x; 1.1946x over previous
#include <cuda_runtime.h>
#include <cuda_bf16.h>
#include <math.h>
#include <stdint.h>

// ---------------- problem constants ----------------
#define NN      20000
#define EE      160000
#define ETOT    (2*EE + NN)
#define FF      128
#define HH      4
#define CC1     128
#define D1      (HH*CC1)       // 512
#define CC2     256
#define GG      64
#define NCLS    10

// ---------------- device scratch ----------------
__device__ __nv_bfloat16 g_xb[NN * FF];
__device__ __nv_bfloat16 g_wt1[D1 * FF];    // W1^T [512][128]
__device__ __nv_bfloat16 g_wt2[CC2 * D1];   // W2^T [256][512]
__device__ __nv_bfloat16 g_h1[NN * D1];
__device__ __nv_bfloat16 g_out1[NN * D1];
__device__ __nv_bfloat16 g_h2[NN * CC2];
__device__ float         g_out2[NN * CC2];
__device__ float g_asrc1[NN * HH];
__device__ float g_adst1[NN * HH];
__device__ float g_asrc2[NN];
__device__ float g_adst2[NN];
__device__ int   g_deg[NN];
__device__ int   g_rowptr[NN + 1];
__device__ int   g_wp[NN];
__device__ int   g_col[ETOT];
__device__ int   g_starts[GG + 1];

// ---------------- CSR build (side stream) ----------------
__global__ void k_init(const int* __restrict__ batch, int n) {
    int i = blockIdx.x * blockDim.x + threadIdx.x;
    if (i < n) {
        g_deg[i] = 1;
        if (i == 0) {
            g_starts[batch[0]] = 0;
            g_starts[GG] = n;
        } else if (batch[i] != batch[i - 1]) {
            g_starts[batch[i]] = i;
        }
    }
}

__global__ void k_count_deg(const int* __restrict__ ei, int E) {
    int j = blockIdx.x * blockDim.x + threadIdx.x;
    if (j < E) {
        atomicAdd(&g_deg[ei[j]], 1);
        atomicAdd(&g_deg[ei[E + j]], 1);
    }
}

__global__ __launch_bounds__(1024) void k_scan_fused(int n) {
    const int t = threadIdx.x, lane = t & 31, wid = t >> 5;
    const int chunk = (n + 1023) / 1024;
    int b = t * chunk, e = min(b + chunk, n);
    if (b > n) b = n;
    if (e < b) e = b;

    int s = 0;
    for (int i = b; i < e; i++) s += g_deg[i];

    int v = s;
#pragma unroll
    for (int o = 1; o < 32; o <<= 1) {
        int x = __shfl_up_sync(0xffffffffu, v, o);
        if (lane >= o) v += x;
    }
    __shared__ int wtot[32];
    if (lane == 31) wtot[wid] = v;
    __syncthreads();
    if (t < 32) {
        int w = wtot[t];
        int u = w;
#pragma unroll
        for (int o = 1; o < 32; o <<= 1) {
            int x = __shfl_up_sync(0xffffffffu, u, o);
            if (t >= o) u += x;
        }
        wtot[t] = u - w;
        if (t == 31) g_rowptr[n] = u;
    }
    __syncthreads();
    int run = v - s + wtot[wid];
    for (int i = b; i < e; i++) {
        int d = g_deg[i];
        g_rowptr[i] = run;
        g_wp[i] = run;
        run += d;
    }
}

__global__ void k_scatter(const int* __restrict__ ei, int E, int n) {
    int j = blockIdx.x * blockDim.x + threadIdx.x;
    if (j < E) {
        int s = ei[j], d = ei[E + j];
        g_col[atomicAdd(&g_wp[d], 1)] = s;
        g_col[atomicAdd(&g_wp[s], 1)] = d;
    } else if (j < E + n) {
        int i = j - E;
        g_col[atomicAdd(&g_wp[i], 1)] = i;
    }
}

// ---------------- merged conversions + zero att accumulators ----------------
__global__ void k_cvt(const float* __restrict__ x, const float* __restrict__ W1,
                      const float* __restrict__ W2, int n) {
    int i = blockIdx.x * blockDim.x + threadIdx.x;
    int totx = n * FF / 2;
    if (i < totx) {
        float2 v = *(const float2*)(x + i * 2);
        *(__nv_bfloat162*)(g_xb + i * 2) = __float22bfloat162_rn(v);
    }
    if (i < D1 * FF) {
        int nc = i / FF, kc = i % FF;
        g_wt1[i] = __float2bfloat16(W1[kc * D1 + nc]);
    }
    if (i < CC2 * D1) {
        int nc = i / D1, kc = i % D1;
        g_wt2[i] = __float2bfloat16(W2[kc * CC2 + nc]);
    }
    if (i < n) {
        *(float4*)&g_asrc1[i * 4] = make_float4(0.f, 0.f, 0.f, 0.f);
        *(float4*)&g_adst1[i * 4] = make_float4(0.f, 0.f, 0.f, 0.f);
        g_asrc2[i] = 0.f;
        g_adst2[i] = 0.f;
    }
}

// ---------------- bf16 tensor-core GEMM (templated N-tile) + att-dot epilogue ----------------
__device__ __forceinline__ void mma_bf16(float c[4], const unsigned a[4], const unsigned b[2]) {
    asm volatile(
        "mma.sync.aligned.m16n8k16.row.col.f32.bf16.bf16.f32 "
        "{%0,%1,%2,%3}, {%4,%5,%6,%7}, {%8,%9}, {%0,%1,%2,%3};"
        : "+f"(c[0]), "+f"(c[1]), "+f"(c[2]), "+f"(c[3])
        : "r"(a[0]), "r"(a[1]), "r"(a[2]), "r"(a[3]), "r"(b[0]), "r"(b[1]));
}

__device__ __forceinline__ void cp16(uint32_t dst, const void* src, int szbytes) {
    asm volatile("cp.async.ca.shared.global [%0], [%1], 16, %2;\n"
                 :: "r"(dst), "l"(src), "r"(szbytes));
}

#define TBM 128
#define BKH 64
#define AST 72
#define ATILE_A (TBM * AST)

template <int NT>
__global__ __launch_bounds__(256) void k_gemm_bf16(const __nv_bfloat16* __restrict__ A,
                                                   const __nv_bfloat16* __restrict__ Bt,
                                                   __nv_bfloat16* __restrict__ C,
                                                   int M, int N, int K,
                                                   const float* __restrict__ attS,
                                                   const float* __restrict__ attD,
                                                   float* __restrict__ outS,
                                                   float* __restrict__ outD,
                                                   int head_shift, int head_stride) {
    constexpr int TBNL = NT * 16;
    constexpr int BTILE = TBNL * AST;
    extern __shared__ __nv_bfloat16 smh[];
    __nv_bfloat16* As = smh;
    __nv_bfloat16* Bs = smh + 2 * ATILE_A;
    uint32_t as_base = (uint32_t)__cvta_generic_to_shared(As);
    uint32_t bs_base = (uint32_t)__cvta_generic_to_shared(Bs);

    int tid = threadIdx.x;
    int bm = blockIdx.y * TBM, bn = blockIdx.x * TBNL;
    int w = tid >> 5, lane = tid & 31;
    int wy = w & 3, wx = w >> 2;
    int gid = lane >> 2, tig = lane & 3;

    float c[2][NT][4];
#pragma unroll
    for (int mt = 0; mt < 2; mt++)
#pragma unroll
        for (int nt = 0; nt < NT; nt++)
#pragma unroll
            for (int r = 0; r < 4; r++) c[mt][nt][r] = 0.f;

    const int KT = K / BKH;

    auto load_tile = [&](int k0, int st) {
#pragma unroll
        for (int i = 0; i < 4; i++) {
            int q = tid + i * 256;
            int row = q >> 3;
            int ch = (q & 7) * 8;
            int gr = bm + row;
            uint32_t d = as_base + (uint32_t)(st * ATILE_A + row * AST + ch) * 2u;
            cp16(d, A + (size_t)gr * K + k0 + ch, (gr < M) ? 16 : 0);
        }
#pragma unroll
        for (int i = 0; i < NT / 2; i++) {
            int q = tid + i * 256;
            int row = q >> 3;
            int ch = (q & 7) * 8;
            uint32_t d = bs_base + (uint32_t)(st * BTILE + row * AST + ch) * 2u;
            cp16(d, Bt + (size_t)(bn + row) * K + k0 + ch, 16);
        }
        asm volatile("cp.async.commit_group;\n");
    };

    load_tile(0, 0);

    for (int it = 0; it < KT; it++) {
        if (it + 1 < KT) {
            load_tile((it + 1) * BKH, (it + 1) & 1);
            asm volatile("cp.async.wait_group 1;\n");
        } else {
            asm volatile("cp.async.wait_group 0;\n");
        }
        __syncthreads();

        const __nv_bfloat16* as = As + (it & 1) * ATILE_A;
        const __nv_bfloat16* bs = Bs + (it & 1) * BTILE;
#pragma unroll
        for (int ks = 0; ks < 4; ks++) {
            int kb = ks * 16;
            unsigned af[2][4], bf[NT][2];
#pragma unroll
            for (int mt = 0; mt < 2; mt++) {
                int r0 = wy * 32 + mt * 16 + gid;
                af[mt][0] = *(const unsigned*)(as + r0 * AST + kb + 2 * tig);
                af[mt][1] = *(const unsigned*)(as + (r0 + 8) * AST + kb + 2 * tig);
                af[mt][2] = *(const unsigned*)(as + r0 * AST + kb + 2 * tig + 8);
                af[mt][3] = *(const unsigned*)(as + (r0 + 8) * AST + kb + 2 * tig + 8);
            }
#pragma unroll
            for (int nt = 0; nt < NT; nt++) {
                int n0 = wx * (NT * 8) + nt * 8 + gid;
                bf[nt][0] = *(const unsigned*)(bs + n0 * AST + kb + 2 * tig);
                bf[nt][1] = *(const unsigned*)(bs + n0 * AST + kb + 2 * tig + 8);
            }
#pragma unroll
            for (int mt = 0; mt < 2; mt++)
#pragma unroll
                for (int nt = 0; nt < NT; nt++) mma_bf16(c[mt][nt], af[mt], bf[nt]);
        }
        __syncthreads();
    }

    int hidx = bn >> head_shift;
#pragma unroll
    for (int mt = 0; mt < 2; mt++) {
        int r_lo = bm + wy * 32 + mt * 16 + gid;
        int r_hi = r_lo + 8;
        float psl = 0.f, pdl = 0.f, psh = 0.f, pdh = 0.f;
#pragma unroll
        for (int nt = 0; nt < NT; nt++) {
            int cl = wx * (NT * 8) + nt * 8 + 2 * tig;
#pragma unroll
            for (int j = 0; j < 2; j++) {
                float s_ = __ldg(&attS[bn + cl + j]);
                float d_ = __ldg(&attD[bn + cl + j]);
                psl += c[mt][nt][j] * s_;     pdl += c[mt][nt][j] * d_;
                psh += c[mt][nt][2 + j] * s_; pdh += c[mt][nt][2 + j] * d_;
            }
            if (r_lo < M) {
                __nv_bfloat162 v = __float22bfloat162_rn(make_float2(c[mt][nt][0], c[mt][nt][1]));
                *(__nv_bfloat162*)&C[(size_t)r_lo * N + bn + cl] = v;
            }
            if (r_hi < M) {
                __nv_bfloat162 v = __float22bfloat162_rn(make_float2(c[mt][nt][2], c[mt][nt][3]));
                *(__nv_bfloat162*)&C[(size_t)r_hi * N + bn + cl] = v;
            }
        }
#pragma unroll
        for (int o = 1; o < 4; o <<= 1) {
            psl += __shfl_xor_sync(0xffffffffu, psl, o);
            pdl += __shfl_xor_sync(0xffffffffu, pdl, o);
            psh += __shfl_xor_sync(0xffffffffu, psh, o);
            pdh += __shfl_xor_sync(0xffffffffu, pdh, o);
        }
        if (tig == 0) {
            if (r_lo < M) {
                atomicAdd(&outS[r_lo * head_stride + hidx], psl);
                atomicAdd(&outD[r_lo * head_stride + hidx], pdl);
            }
            if (r_hi < M) {
                atomicAdd(&outS[r_hi * head_stride + hidx], psh);
                atomicAdd(&outD[r_hi * head_stride + hidx], pdh);
            }
        }
    }
}

#define GEMM_SMEM_NT4 (2 * (ATILE_A + 64 * AST) * 2)   // 55296

// ---------------- fused softmax + aggregation (smem-staged exp) ----------------
__device__ __forceinline__ float lrelu(float e) { return (e > 0.f) ? e : 0.2f * e; }

// layer1: block 128, warp w = head w, thread t -> channels 4t..4t+3
__global__ void k_gat1_agg(const __nv_bfloat16* __restrict__ h, const float* __restrict__ bias,
                           __nv_bfloat16* __restrict__ out) {
    int d = blockIdx.x;
    int t = threadIdx.x, w = t >> 5, lane = t & 31;
    int beg = g_rowptr[d], end = g_rowptr[d + 1];
    float ad = g_adst1[d * HH + w];

    __shared__ float ee_s[32][5];   // [edge-in-chunk][head], pad -> conflict-free
    __shared__ int   col_s[32];

    float sum = 0.f;
    float ax = 0.f, ay = 0.f, az = 0.f, aw = 0.f;

    for (int c0 = beg; c0 < end; c0 += 32) {
        int m = min(32, end - c0);
        // phase A: each warp computes exp for its head, one edge per lane
        if (lane < m) {
            int s = g_col[c0 + lane];
            if (w == 0) col_s[lane] = s;
            float ee = __expf(lrelu(g_asrc1[s * HH + w] + ad));
            ee_s[lane][w] = ee;
            sum += ee;
        }
        __syncthreads();
        // phase B: unnormalized aggregation, broadcast reads from smem
        for (int j = 0; j < m; j++) {
            int s = col_s[j];
            float a = ee_s[j][w];
            uint2 r = *(const uint2*)(h + (size_t)s * D1 + t * 4);
            float2 p = __bfloat1622float2(*reinterpret_cast<__nv_bfloat162*>(&r.x));
            float2 q = __bfloat1622float2(*reinterpret_cast<__nv_bfloat162*>(&r.y));
            ax += p.x * a; ay += p.y * a; az += q.x * a; aw += q.y * a;
        }
        __syncthreads();
    }

#pragma unroll
    for (int o = 16; o > 0; o >>= 1) sum += __shfl_xor_sync(0xffffffffu, sum, o);
    float inv = 1.f / sum;

    float4 b = *(const float4*)&bias[t * 4];
    __nv_bfloat162 v0 = __float22bfloat162_rn(
        make_float2(fmaxf(ax * inv + b.x, 0.f), fmaxf(ay * inv + b.y, 0.f)));
    __nv_bfloat162 v1 = __float22bfloat162_rn(
        make_float2(fmaxf(az * inv + b.z, 0.f), fmaxf(aw * inv + b.w, 0.f)));
    uint2 pack;
    pack.x = *reinterpret_cast<unsigned*>(&v0);
    pack.y = *reinterpret_cast<unsigned*>(&v1);
    *(uint2*)&out[(size_t)d * D1 + t * 4] = pack;
}

// layer2: block 64 (2 warps), single head
__global__ void k_gat2_agg(const __nv_bfloat16* __restrict__ h, const float* __restrict__ bias,
                           float* __restrict__ out) {
    int d = blockIdx.x;
    int t = threadIdx.x, lane = t & 31, w = t >> 5;
    int beg = g_rowptr[d], end = g_rowptr[d + 1];
    float ad = g_adst2[d];

    __shared__ float ee_s[64];
    __shared__ int   col_s[64];
    __shared__ float wsum[2];

    float sum = 0.f;
    float ax = 0.f, ay = 0.f, az = 0.f, aw = 0.f;

    for (int c0 = beg; c0 < end; c0 += 64) {
        int m = min(64, end - c0);
        if (t < m) {
            int s = g_col[c0 + t];
            col_s[t] = s;
            float ee = __expf(lrelu(g_asrc2[s] + ad));
            ee_s[t] = ee;
            sum += ee;
        }
        __syncthreads();
        for (int j = 0; j < m; j++) {
            int s = col_s[j];
            float a = ee_s[j];
            uint2 r = *(const uint2*)(h + (size_t)s * CC2 + t * 4);
            float2 p = __bfloat1622float2(*reinterpret_cast<__nv_bfloat162*>(&r.x));
            float2 q = __bfloat1622float2(*reinterpret_cast<__nv_bfloat162*>(&r.y));
            ax += p.x * a; ay += p.y * a; az += q.x * a; aw += q.y * a;
        }
        __syncthreads();
    }

#pragma unroll
    for (int o = 16; o > 0; o >>= 1) sum += __shfl_xor_sync(0xffffffffu, sum, o);
    if (lane == 0) wsum[w] = sum;
    __syncthreads();
    float inv = 1.f / (wsum[0] + wsum[1]);

    float4 b = *(const float4*)&bias[t * 4];
    *(float4*)&out[(size_t)d * CC2 + t * 4] =
        make_float4(ax * inv + b.x, ay * inv + b.y, az * inv + b.z, aw * inv + b.w);
}

// ---------------- fused pool + MLP head (1024 threads, 4-way row split) ----------------
__global__ __launch_bounds__(1024) void k_poolhead(const float* __restrict__ x,
                                                   const float* __restrict__ w1,
                                                   const float* __restrict__ b1,
                                                   const float* __restrict__ w2,
                                                   const float* __restrict__ b2,
                                                   float* __restrict__ out) {
    int g = blockIdx.x;
    int t = threadIdx.x;
    int c = t & 255, seg = t >> 8;
    __shared__ float pmax[4][CC2];
    __shared__ float pool[CC2];
    __shared__ float s1[64];
    __shared__ float logits[NCLS];

    int beg = g_starts[g], end = g_starts[g + 1];
    float m = -1e30f;
    for (int i = beg + seg; i < end; i += 4) m = fmaxf(m, x[(size_t)i * CC2 + c]);
    pmax[seg][c] = m;
    __syncthreads();
    if (t < CC2)
        pool[t] = fmaxf(fmaxf(pmax[0][t], pmax[1][t]), fmaxf(pmax[2][t], pmax[3][t]));
    __syncthreads();

    if (t < 64) {
        float acc = b1[t];
        for (int k = 0; k < CC2; k++) acc += pool[k] * w1[k * 64 + t];
        s1[t] = fmaxf(acc, 0.f);
    }
    __syncthreads();
    if (t < NCLS) {
        float l = b2[t];
        for (int k = 0; k < 64; k++) l += s1[k] * w2[k * NCLS + t];
        logits[t] = l;
    }
    __syncthreads();
    if (t < NCLS) {
        float mm = -1e30f;
        for (int j = 0; j < NCLS; j++) mm = fmaxf(mm, logits[j]);
        float se = 0.f;
        for (int j = 0; j < NCLS; j++) se += expf(logits[j] - mm);
        out[g * NCLS + t] = logits[t] - mm - logf(se);
    }
}

// ---------------- launch ----------------
extern "C" void kernel_launch(void* const* d_in, const int* in_sizes, int n_in,
                              void* d_out, int out_size) {
    const float* x        = (const float*)d_in[0];
    const int*   ei       = (const int*)d_in[1];
    const int*   batch    = (const int*)d_in[2];
    const float* W1       = (const float*)d_in[3];
    const float* att_src1 = (const float*)d_in[4];
    const float* att_dst1 = (const float*)d_in[5];
    const float* b1       = (const float*)d_in[6];
    const float* W2       = (const float*)d_in[7];
    const float* att_src2 = (const float*)d_in[8];
    const float* att_dst2 = (const float*)d_in[9];
    const float* b2       = (const float*)d_in[10];
    const float* fc1_w    = (const float*)d_in[11];
    const float* fc1_b    = (const float*)d_in[12];
    const float* fc2_w    = (const float*)d_in[13];
    const float* fc2_b    = (const float*)d_in[14];
    float* out = (float*)d_out;

    const int n = in_sizes[2];
    const int E = in_sizes[1] / 2;

    static cudaStream_t s1;
    static cudaEvent_t e_fork, e_join;
    static int inited = 0;
    if (!inited) {
        cudaFuncSetAttribute(k_gemm_bf16<4>, cudaFuncAttributeMaxDynamicSharedMemorySize,
                             GEMM_SMEM_NT4);
        cudaStreamCreateWithFlags(&s1, cudaStreamNonBlocking);
        cudaEventCreateWithFlags(&e_fork, cudaEventDisableTiming);
        cudaEventCreateWithFlags(&e_join, cudaEventDisableTiming);
        inited = 1;
    }

    __nv_bfloat16 *xb, *wt1, *wt2, *h1, *out1, *h2;
    float *out2, *asrc1, *adst1, *asrc2, *adst2;
    cudaGetSymbolAddress((void**)&xb, g_xb);
    cudaGetSymbolAddress((void**)&wt1, g_wt1);
    cudaGetSymbolAddress((void**)&wt2, g_wt2);
    cudaGetSymbolAddress((void**)&h1, g_h1);
    cudaGetSymbolAddress((void**)&out1, g_out1);
    cudaGetSymbolAddress((void**)&h2, g_h2);
    cudaGetSymbolAddress((void**)&out2, g_out2);
    cudaGetSymbolAddress((void**)&asrc1, g_asrc1);
    cudaGetSymbolAddress((void**)&adst1, g_adst1);
    cudaGetSymbolAddress((void**)&asrc2, g_asrc2);
    cudaGetSymbolAddress((void**)&adst2, g_adst2);

    // ---- fork: CSR build on side stream ----
    cudaEventRecord(e_fork, 0);
    cudaStreamWaitEvent(s1, e_fork, 0);
    k_init<<<(n + 255) / 256, 256, 0, s1>>>(batch, n);
    k_count_deg<<<(E + 255) / 256, 256, 0, s1>>>(ei, E);
    k_scan_fused<<<1, 1024, 0, s1>>>(n);
    k_scatter<<<(E + n + 255) / 256, 256, 0, s1>>>(ei, E, n);
    cudaEventRecord(e_join, s1);

    // ---- main: convert inputs, GEMM1 (+attdot1 epilogue) ----
    k_cvt<<<(n * FF / 2 + 255) / 256, 256>>>(x, W1, W2, n);
    {
        dim3 grid(D1 / 64, (n + TBM - 1) / TBM);
        k_gemm_bf16<4><<<grid, 256, GEMM_SMEM_NT4>>>(xb, wt1, h1, n, D1, FF,
                                                     att_src1, att_dst1, asrc1, adst1,
                                                     7, HH);
    }

    // ---- join: aggregation needs CSR ----
    cudaStreamWaitEvent(0, e_join, 0);
    k_gat1_agg<<<n, 128>>>(h1, b1, out1);

    // ---- layer 2 (GEMM2 + attdot2 epilogue) ----
    {
        dim3 grid(CC2 / 64, (n + TBM - 1) / TBM);
        k_gemm_bf16<4><<<grid, 256, GEMM_SMEM_NT4>>>(out1, wt2, h2, n, CC2, D1,
                                                     att_src2, att_dst2, asrc2, adst2,
                                                     8, 1);
    }
    k_gat2_agg<<<n, 64>>>(h2, b2, out2);

    // ---- pool + head ----
    k_poolhead<<<GG, 1024>>>(out2, fc1_w, fc1_b, fc2_w, fc2_b, out);
}